// round 7
// baseline (speedup 1.0000x reference)
#include <cuda_runtime.h>
#include <cuda_bf16.h>

#define CCH   256
#define HH    360
#define WW    360
#define NPTS  1024
#define CPB   16

typedef unsigned long long ull;

// Scratch: a1[m][k] = f1 @ w3 ; a2p[n][k] = b3[k] - (f2 @ w3)[n][k]
__device__ float g_a1[NPTS * 32];
__device__ float g_a2p[NPTS * 32];

#define FFMA2(acc, x, w) \
    asm("fma.rn.f32x2 %0, %1, %2, %0;" : "+l"(acc) : "l"(x), "l"(w))
#define FADD2(d, a, b) \
    asm("add.rn.f32x2 %0, %1, %2;" : "=l"(d) : "l"(a), "l"(b))

__device__ __forceinline__ ull pack2(float a, float b) {
    ull r;
    asm("mov.b64 %0, {%1, %2};" : "=l"(r) : "f"(a), "f"(b));
    return r;
}
__device__ __forceinline__ float2 unpack2(ull v) {
    float2 f;
    asm("mov.b64 {%0, %1}, %2;" : "=f"(f.x), "=f"(f.y) : "l"(v));
    return f;
}

// ---------------------------------------------------------------------------
// Kernel 1: gather + 256->256->128 MLP (relu) + @w3 projection (b3 folded).
// 16 centers/block, 512 threads, 128 blocks, split-K partial sums.
// CHANNEL-PAIR f32x2 packing: FFMA2 halves = even/odd channel partial sums,
// so neither operand needs duplication (no pack MOVs in the hot loop).
// Shared (48KB, overlaid):
//   smemA: xs[16][256] floats  -> w3s[128*32] after layer1
//   smemB: part1[16][256]      -> part2[16][128] | h2s[16][128]
//   smemC: h1s[16][256]
// ---------------------------------------------------------------------------
__global__ __launch_bounds__(512) void project_kernel(
    const float* __restrict__ feature,
    const int*   __restrict__ idx1,
    const int*   __restrict__ idx2,
    const float* __restrict__ w1, const float* __restrict__ b1,
    const float* __restrict__ w2, const float* __restrict__ b2,
    const float* __restrict__ w3, const float* __restrict__ b3)
{
    __shared__ float smemA[CPB * 256];   // 16KB
    __shared__ float smemB[CPB * 256];   // 16KB
    __shared__ float smemC[CPB * 256];   // 16KB

    float (*xs)[256]   = (float (*)[256])smemA;
    float*  w3s        = smemA;
    float (*part1)[256] = (float (*)[256])smemB;
    float (*part2)[128] = (float (*)[128])smemB;             // 8KB
    float (*h2s)[128]   = (float (*)[128])(smemB + 2048);    // 8KB
    float (*h1s)[256]   = (float (*)[256])smemC;

    const int tid = threadIdx.x;
    const int g0  = blockIdx.x * CPB;
    const bool frame2 = (g0 >= NPTS);
    const int* __restrict__ idx = frame2 ? idx2 : idx1;
    const int  i0 = frame2 ? (g0 - NPTS) : g0;

    // ---- gather: 16 centers x 256 channels = 4096 loads over 512 threads
    #pragma unroll
    for (int i = 0; i < 8; i++) {
        int e  = tid + i * 512;
        int t  = e >> 8;
        int ch = e & 255;
        int b  = __ldg(&idx[i0 + t]);
        int hh = __ldg(&idx[NPTS + i0 + t]);
        int ww = __ldg(&idx[2 * NPTS + i0 + t]);
        long off = (((long)b * CCH + ch) * HH + hh) * (long)WW + ww;
        xs[t][ch] = __ldg(&feature[off]);
    }
    __syncthreads();

    // ---- layer 1: h1 = relu(x @ w1 + b1)
    // thread (j = tid&255, h = tid>>8): output col j, channel half h.
    {
        const int j = tid & 255;
        const int h = tid >> 8;
        const int cbase = h * 128;
        ull acc[CPB];
        {
            ull init = h ? 0ULL : pack2(b1[j], 0.0f);
            #pragma unroll
            for (int p = 0; p < CPB; p++) acc[p] = init;
        }
        #pragma unroll 2
        for (int c0 = 0; c0 < 128; c0 += 4) {
            int c = cbase + c0;
            ull wp01 = pack2(w1[(c + 0) * 256 + j], w1[(c + 1) * 256 + j]);
            ull wp23 = pack2(w1[(c + 2) * 256 + j], w1[(c + 3) * 256 + j]);
            #pragma unroll
            for (int p = 0; p < CPB; p++) {
                ulonglong2 x = *(const ulonglong2*)&xs[p][c];   // 4 channels
                FFMA2(acc[p], x.x, wp01);
                FFMA2(acc[p], x.y, wp23);
            }
        }
        if (h) {
            #pragma unroll
            for (int p = 0; p < CPB; p++) {
                float2 f = unpack2(acc[p]);
                part1[p][j] = f.x + f.y;
            }
        }
        __syncthreads();   // xs dead; part1 ready
        if (!h) {
            #pragma unroll
            for (int p = 0; p < CPB; p++) {
                float2 f = unpack2(acc[p]);
                h1s[p][j] = fmaxf(f.x + f.y + part1[p][j], 0.0f);
            }
        } else {
            // h==1 threads stage w3 into the freed xs region
            const float4* src = (const float4*)w3;
            float4* dst = (float4*)w3s;
            int l = tid - 256;
            #pragma unroll
            for (int i = 0; i < 4; i++) dst[l + i * 256] = src[l + i * 256];
        }
    }
    __syncthreads();

    // ---- layer 2: h2 = relu(h1 @ w2 + b2)
    // thread (j2 = tid&127, q = tid>>7): qc = channel half, qp = center half.
    {
        const int j2 = tid & 127;
        const int q  = tid >> 7;
        const int qc = q & 1;
        const int qp = q >> 1;
        const int cbase = qc * 128;
        const int pb = qp * 8;        // centers pb..pb+7
        ull acc[8];
        {
            ull init = qc ? 0ULL : pack2(b2[j2], 0.0f);
            #pragma unroll
            for (int u = 0; u < 8; u++) acc[u] = init;
        }
        #pragma unroll 2
        for (int c0 = 0; c0 < 128; c0 += 4) {
            int c = cbase + c0;
            ull wp01 = pack2(w2[(c + 0) * 128 + j2], w2[(c + 1) * 128 + j2]);
            ull wp23 = pack2(w2[(c + 2) * 128 + j2], w2[(c + 3) * 128 + j2]);
            #pragma unroll
            for (int u = 0; u < 8; u++) {
                ulonglong2 x = *(const ulonglong2*)&h1s[pb + u][c];
                FFMA2(acc[u], x.x, wp01);
                FFMA2(acc[u], x.y, wp23);
            }
        }
        if (qc) {
            #pragma unroll
            for (int u = 0; u < 8; u++) {
                float2 f = unpack2(acc[u]);
                part2[pb + u][j2] = f.x + f.y;
            }
        }
        __syncthreads();   // part1 dead; part2 ready
        if (!qc) {
            #pragma unroll
            for (int u = 0; u < 8; u++) {
                float2 f = unpack2(acc[u]);
                h2s[pb + u][j2] = fmaxf(f.x + f.y + part2[pb + u][j2], 0.0f);
            }
        }
    }
    __syncthreads();

    // ---- layer 3 (projection): a = h2 @ w3, b3 folded for frame 2.
    // 16 warps, warp w -> center w; lane k -> output dim k.
    {
        const int w = tid >> 5;       // 0..15 = center
        const int k = tid & 31;
        float acc0 = 0.0f, acc1 = 0.0f, acc2 = 0.0f, acc3 = 0.0f;
        #pragma unroll 8
        for (int d = 0; d < 128; d += 4) {
            float4 hv = *(const float4*)&h2s[w][d];   // broadcast LDS.128
            acc0 = fmaf(hv.x, w3s[(d + 0) * 32 + k], acc0);
            acc1 = fmaf(hv.y, w3s[(d + 1) * 32 + k], acc1);
            acc2 = fmaf(hv.z, w3s[(d + 2) * 32 + k], acc2);
            acc3 = fmaf(hv.w, w3s[(d + 3) * 32 + k], acc3);
        }
        float r = (acc0 + acc1) + (acc2 + acc3);
        int gg = g0 + w;
        if (!frame2) {
            g_a1[gg * 32 + k] = r;
        } else {
            g_a2p[(gg - NPTS) * 32 + k] = b3[k] - r;
        }
    }
}

// ---------------------------------------------------------------------------
// Kernel 2: out[m,n] = b4 + sum_k relu(a1[m,k] + a2p[n,k]) * w4[k]
// 256 threads (each owns one n), m-tile 16, grid (4, 64) = 256 CTAs,
// 2 CTAs/SM forced via launch bounds (16 warps resident + wave balance).
// ---------------------------------------------------------------------------
__global__ __launch_bounds__(256, 2) void pair_kernel(
    const float* __restrict__ w4,
    const float* __restrict__ b4,
    float*       __restrict__ out)
{
    __shared__ float a1s[16 * 32];   // 2KB

    const int tid = threadIdx.x;
    const int n   = blockIdx.x * 256 + tid;
    const int m0  = blockIdx.y * 16;

    // stage a1 tile (16 x 32 = 512 floats) via float4
    if (tid < 128)
        ((float4*)a1s)[tid] = ((const float4*)(g_a1 + m0 * 32))[tid];

    // a2p row + w4, packed as 16 f32x2 pairs each
    ull a2p[16], w4p[16];
    {
        const float4* ar = (const float4*)(g_a2p + (long)n * 32);
        const float4* wr = (const float4*)w4;
        #pragma unroll
        for (int v = 0; v < 8; v++) {
            float4 a = ar[v];
            float4 w = wr[v];
            a2p[2 * v]     = pack2(a.x, a.y);
            a2p[2 * v + 1] = pack2(a.z, a.w);
            w4p[2 * v]     = pack2(w.x, w.y);
            w4p[2 * v + 1] = pack2(w.z, w.w);
        }
    }
    const float bias = b4[0];
    __syncthreads();

    #pragma unroll 4
    for (int m = 0; m < 16; m++) {
        const ulonglong2* ap = (const ulonglong2*)&a1s[m * 32];
        ull acc0 = pack2(bias, 0.0f), acc1 = 0ULL;
        #pragma unroll
        for (int v = 0; v < 8; v++) {      // 8 chunks x 4 dims = 32 dims
            ulonglong2 qa = ap[v];         // a1 dims 4v .. 4v+3
            ull s0, s1;
            FADD2(s0, qa.x, a2p[2 * v + 0]);
            FADD2(s1, qa.y, a2p[2 * v + 1]);
            float2 f0 = unpack2(s0), f1 = unpack2(s1);
            s0 = pack2(fmaxf(f0.x, 0.0f), fmaxf(f0.y, 0.0f));
            s1 = pack2(fmaxf(f1.x, 0.0f), fmaxf(f1.y, 0.0f));
            FFMA2(acc0, s0, w4p[2 * v + 0]);
            FFMA2(acc1, s1, w4p[2 * v + 1]);
        }
        float2 r0 = unpack2(acc0), r1 = unpack2(acc1);
        out[(long)(m0 + m) * 1024 + n] = (r0.x + r0.y) + (r1.x + r1.y);
    }
}

// ---------------------------------------------------------------------------
extern "C" void kernel_launch(void* const* d_in, const int* in_sizes, int n_in,
                              void* d_out, int out_size)
{
    const float* feature = (const float*)d_in[0];
    const int*   idx1    = (const int*)  d_in[1];
    const int*   idx2    = (const int*)  d_in[2];
    const float* w1      = (const float*)d_in[3];
    const float* b1      = (const float*)d_in[4];
    const float* w2      = (const float*)d_in[5];
    const float* b2      = (const float*)d_in[6];
    const float* w3      = (const float*)d_in[7];
    const float* b3      = (const float*)d_in[8];
    const float* w4      = (const float*)d_in[9];
    const float* b4      = (const float*)d_in[10];
    float* out = (float*)d_out;

    project_kernel<<<(2 * NPTS) / CPB, 512>>>(feature, idx1, idx2,
                                              w1, b1, w2, b2, w3, b3);
    dim3 grid2(NPTS / 256, NPTS / 16);
    pair_kernel<<<grid2, 256>>>(w4, b4, out);
}

// round 8
// speedup vs baseline: 1.5109x; 1.5109x over previous
#include <cuda_runtime.h>
#include <cuda_bf16.h>

#define CCH   256
#define HH    360
#define WW    360
#define NPTS  1024
#define CPB   16
#define NPAIR (CPB / 2)   // 8 center pairs per block

typedef unsigned long long ull;

// Scratch: a1[m][k] = f1 @ w3 ; a2p[n][k] = b3[k] - (f2 @ w3)[n][k]
__device__ float g_a1[NPTS * 32];
__device__ float g_a2p[NPTS * 32];

#define FFMA2(acc, x, w) \
    asm("fma.rn.f32x2 %0, %1, %2, %0;" : "+l"(acc) : "l"(x), "l"(w))
#define FADD2(d, a, b) \
    asm("add.rn.f32x2 %0, %1, %2;" : "=l"(d) : "l"(a), "l"(b))

__device__ __forceinline__ ull pack2(float a, float b) {
    ull r;
    asm("mov.b64 %0, {%1, %2};" : "=l"(r) : "f"(a), "f"(b));
    return r;
}
__device__ __forceinline__ float2 unpack2(ull v) {
    float2 f;
    asm("mov.b64 {%0, %1}, %2;" : "=f"(f.x), "=f"(f.y) : "l"(v));
    return f;
}

// ---------------------------------------------------------------------------
// Kernel 1: gather + 256->256->128 MLP (relu) + @w3 projection (b3 folded).
// 16 centers per block (8 f32x2 center-pairs), 512 threads, 128 blocks.
// Split-K partial sums; measured 23.3us in round 5. No prefetch (regressed),
// no channel-pair packing (regressed).
// Shared memory (48KB, overlaid):
//   smemA: xs2[8][256]  -> w3s[128*32] after layer1
//   smemB: part1[8][256] -> part2[8][128] | h2p[8][128]
//   smemC: h1p[8][256]
// ---------------------------------------------------------------------------
__global__ __launch_bounds__(512) void project_kernel(
    const float* __restrict__ feature,
    const int*   __restrict__ idx1,
    const int*   __restrict__ idx2,
    const float* __restrict__ w1, const float* __restrict__ b1,
    const float* __restrict__ w2, const float* __restrict__ b2,
    const float* __restrict__ w3, const float* __restrict__ b3)
{
    __shared__ float2 smemA[NPAIR * 256];   // 16KB
    __shared__ float2 smemB[NPAIR * 256];   // 16KB
    __shared__ float2 smemC[NPAIR * 256];   // 16KB

    float2 (*xs2)[256] = (float2 (*)[256])smemA;
    float*  w3s        = (float*)smemA;
    float2 (*part1)[256] = (float2 (*)[256])smemB;
    float2* part2      = smemB;              // [8][128] float2 = 8KB
    float2 (*h2p)[128] = (float2 (*)[128])(smemB + 1024); // 8KB
    float2 (*h1p)[256] = (float2 (*)[256])smemC;

    const int tid = threadIdx.x;
    const int g0  = blockIdx.x * CPB;
    const bool frame2 = (g0 >= NPTS);
    const int* __restrict__ idx = frame2 ? idx2 : idx1;
    const int  i0 = frame2 ? (g0 - NPTS) : g0;

    // ---- gather: 16 centers x 256 channels = 4096 loads over 512 threads
    #pragma unroll
    for (int i = 0; i < 8; i++) {
        int e  = tid + i * 512;
        int t  = e >> 8;
        int ch = e & 255;
        int b  = __ldg(&idx[i0 + t]);
        int hh = __ldg(&idx[NPTS + i0 + t]);
        int ww = __ldg(&idx[2 * NPTS + i0 + t]);
        long off = (((long)b * CCH + ch) * HH + hh) * (long)WW + ww;
        ((float*)&xs2[t >> 1][ch])[t & 1] = __ldg(&feature[off]);
    }
    __syncthreads();

    // ---- layer 1: h1 = relu(x @ w1 + b1)
    // thread (j = tid&255, h = tid>>8): output col j, channel half h.
    {
        const int j = tid & 255;
        const int h = tid >> 8;
        const int cbase = h * 128;
        ull acc[NPAIR];
        {
            ull init;
            if (h) init = 0ULL;
            else { float bb = b1[j]; init = pack2(bb, bb); }
            #pragma unroll
            for (int p = 0; p < NPAIR; p++) acc[p] = init;
        }
        #pragma unroll 2
        for (int c0 = 0; c0 < 128; c0 += 4) {
            int c = cbase + c0;
            float v0 = w1[(c + 0) * 256 + j];
            float v1 = w1[(c + 1) * 256 + j];
            float v2 = w1[(c + 2) * 256 + j];
            float v3 = w1[(c + 3) * 256 + j];
            ull p0 = pack2(v0, v0), p1 = pack2(v1, v1);
            ull p2 = pack2(v2, v2), p3 = pack2(v3, v3);
            #pragma unroll
            for (int p = 0; p < NPAIR; p++) {
                ulonglong2 qa = *(const ulonglong2*)&xs2[p][c];
                ulonglong2 qb = *(const ulonglong2*)&xs2[p][c + 2];
                FFMA2(acc[p], qa.x, p0);
                FFMA2(acc[p], qa.y, p1);
                FFMA2(acc[p], qb.x, p2);
                FFMA2(acc[p], qb.y, p3);
            }
        }
        if (h) {
            #pragma unroll
            for (int p = 0; p < NPAIR; p++)
                part1[p][j] = unpack2(acc[p]);
        }
        __syncthreads();   // xs2 dead; part1 ready
        if (!h) {
            #pragma unroll
            for (int p = 0; p < NPAIR; p++) {
                float2 f = unpack2(acc[p]);
                float2 g = part1[p][j];
                h1p[p][j] = make_float2(fmaxf(f.x + g.x, 0.0f),
                                        fmaxf(f.y + g.y, 0.0f));
            }
        } else {
            // h==1 threads stage w3 into the freed xs2 region
            const float4* src = (const float4*)w3;
            float4* dst = (float4*)w3s;
            int l = tid - 256;
            #pragma unroll
            for (int i = 0; i < 4; i++) dst[l + i * 256] = src[l + i * 256];
        }
    }
    __syncthreads();

    // ---- layer 2: h2 = relu(h1 @ w2 + b2)
    // thread (j2 = tid&127, q = tid>>7): qc = channel half, qp = pair half.
    {
        const int j2 = tid & 127;
        const int q  = tid >> 7;
        const int qc = q & 1;
        const int qp = q >> 1;
        const int cbase = qc * 128;
        const int pb = qp * 4;
        ull acc[4];
        {
            ull init;
            if (qc) init = 0ULL;
            else { float bb = b2[j2]; init = pack2(bb, bb); }
            #pragma unroll
            for (int u = 0; u < 4; u++) acc[u] = init;
        }
        #pragma unroll 2
        for (int c0 = 0; c0 < 128; c0 += 4) {
            int c = cbase + c0;
            float v0 = w2[(c + 0) * 128 + j2];
            float v1 = w2[(c + 1) * 128 + j2];
            float v2 = w2[(c + 2) * 128 + j2];
            float v3 = w2[(c + 3) * 128 + j2];
            ull p0 = pack2(v0, v0), p1 = pack2(v1, v1);
            ull p2 = pack2(v2, v2), p3 = pack2(v3, v3);
            #pragma unroll
            for (int u = 0; u < 4; u++) {
                int p = pb + u;
                ulonglong2 qa = *(const ulonglong2*)&h1p[p][c];
                ulonglong2 qb = *(const ulonglong2*)&h1p[p][c + 2];
                FFMA2(acc[u], qa.x, p0);
                FFMA2(acc[u], qa.y, p1);
                FFMA2(acc[u], qb.x, p2);
                FFMA2(acc[u], qb.y, p3);
            }
        }
        if (qc) {
            #pragma unroll
            for (int u = 0; u < 4; u++)
                part2[(qp * 4 + u) * 128 + j2] = unpack2(acc[u]);
        }
        __syncthreads();   // part1 dead; part2 ready
        if (!qc) {
            #pragma unroll
            for (int u = 0; u < 4; u++) {
                float2 f = unpack2(acc[u]);
                float2 g = part2[(qp * 4 + u) * 128 + j2];
                h2p[pb + u][j2] = make_float2(fmaxf(f.x + g.x, 0.0f),
                                              fmaxf(f.y + g.y, 0.0f));
            }
        }
    }
    __syncthreads();

    // ---- layer 3 (projection): a = h2 @ w3, b3 folded for frame 2.
    // 16 warps, warp w -> center w; lane k -> output dim k.
    {
        const int w = tid >> 5;       // 0..15 = center
        const int k = tid & 31;
        const int p = w >> 1;
        const int hl = w & 1;
        float acc0 = 0.0f, acc1 = 0.0f, acc2 = 0.0f, acc3 = 0.0f;
        #pragma unroll 8
        for (int d = 0; d < 128; d += 4) {
            float hv0 = ((const float*)&h2p[p][d + 0])[hl];
            float hv1 = ((const float*)&h2p[p][d + 1])[hl];
            float hv2 = ((const float*)&h2p[p][d + 2])[hl];
            float hv3 = ((const float*)&h2p[p][d + 3])[hl];
            acc0 = fmaf(hv0, w3s[(d + 0) * 32 + k], acc0);
            acc1 = fmaf(hv1, w3s[(d + 1) * 32 + k], acc1);
            acc2 = fmaf(hv2, w3s[(d + 2) * 32 + k], acc2);
            acc3 = fmaf(hv3, w3s[(d + 3) * 32 + k], acc3);
        }
        float r = (acc0 + acc1) + (acc2 + acc3);
        int gg = g0 + w;
        if (!frame2) {
            g_a1[gg * 32 + k] = r;
        } else {
            g_a2p[(gg - NPTS) * 32 + k] = b3[k] - r;
        }
    }
}

// ---------------------------------------------------------------------------
// Kernel 2: out[m,n] = b4 + sum_k relu(a1[m,k] + a2p[n,k]) * w4[k]
// 256 threads (each owns one n), m-tile 16, grid (4, 64) = 256 CTAs.
// Round-2/3 shape (measured ~10us); no minBlocks hint.
// ---------------------------------------------------------------------------
__global__ __launch_bounds__(256) void pair_kernel(
    const float* __restrict__ w4,
    const float* __restrict__ b4,
    float*       __restrict__ out)
{
    __shared__ float a1s[16 * 32];   // 2KB

    const int tid = threadIdx.x;
    const int n   = blockIdx.x * 256 + tid;
    const int m0  = blockIdx.y * 16;

    // stage a1 tile (16 x 32 = 512 floats) via float4
    if (tid < 128)
        ((float4*)a1s)[tid] = ((const float4*)(g_a1 + m0 * 32))[tid];

    // a2p row + w4, packed as 16 f32x2 pairs each
    ull a2p[16], w4p[16];
    {
        const float4* ar = (const float4*)(g_a2p + (long)n * 32);
        const float4* wr = (const float4*)w4;
        #pragma unroll
        for (int v = 0; v < 8; v++) {
            float4 a = ar[v];
            float4 w = wr[v];
            a2p[2 * v]     = pack2(a.x, a.y);
            a2p[2 * v + 1] = pack2(a.z, a.w);
            w4p[2 * v]     = pack2(w.x, w.y);
            w4p[2 * v + 1] = pack2(w.z, w.w);
        }
    }
    const float bias = b4[0];
    __syncthreads();

    #pragma unroll 2
    for (int m = 0; m < 16; m++) {
        const ulonglong2* ap = (const ulonglong2*)&a1s[m * 32];
        ull acc0 = pack2(bias, 0.0f), acc1 = 0ULL;
        #pragma unroll
        for (int v = 0; v < 8; v++) {      // 8 chunks x 4 dims = 32 dims
            ulonglong2 qa = ap[v];         // a1 dims 4v .. 4v+3
            ull s0, s1;
            FADD2(s0, qa.x, a2p[2 * v + 0]);
            FADD2(s1, qa.y, a2p[2 * v + 1]);
            float2 f0 = unpack2(s0), f1 = unpack2(s1);
            s0 = pack2(fmaxf(f0.x, 0.0f), fmaxf(f0.y, 0.0f));
            s1 = pack2(fmaxf(f1.x, 0.0f), fmaxf(f1.y, 0.0f));
            FFMA2(acc0, s0, w4p[2 * v + 0]);
            FFMA2(acc1, s1, w4p[2 * v + 1]);
        }
        float2 r0 = unpack2(acc0), r1 = unpack2(acc1);
        out[(long)(m0 + m) * 1024 + n] = (r0.x + r0.y) + (r1.x + r1.y);
    }
}

// ---------------------------------------------------------------------------
extern "C" void kernel_launch(void* const* d_in, const int* in_sizes, int n_in,
                              void* d_out, int out_size)
{
    const float* feature = (const float*)d_in[0];
    const int*   idx1    = (const int*)  d_in[1];
    const int*   idx2    = (const int*)  d_in[2];
    const float* w1      = (const float*)d_in[3];
    const float* b1      = (const float*)d_in[4];
    const float* w2      = (const float*)d_in[5];
    const float* b2      = (const float*)d_in[6];
    const float* w3      = (const float*)d_in[7];
    const float* b3      = (const float*)d_in[8];
    const float* w4      = (const float*)d_in[9];
    const float* b4      = (const float*)d_in[10];
    float* out = (float*)d_out;

    project_kernel<<<(2 * NPTS) / CPB, 512>>>(feature, idx1, idx2,
                                              w1, b1, w2, b2, w3, b3);
    dim3 grid2(NPTS / 256, NPTS / 16);
    pair_kernel<<<grid2, 256>>>(w4, b4, out);
}